// round 1
// baseline (speedup 1.0000x reference)
#include <cuda_runtime.h>
#include <cstdint>
#include <math.h>

#define T_TOK 2048
#define HID   2048
#define INTER 1408
#define NEXP  8

// ---------------- device scratch (no allocations allowed) ----------------
__device__ int   g_cnt[NEXP];
__device__ int   g_tok [NEXP * T_TOK];   // token id per (expert, pos)
__device__ int   g_slot[NEXP * T_TOK];   // output slot (2t or 2t+1)
__device__ float g_wt  [NEXP * T_TOK];   // routing weight
__device__ float g_hmid[(size_t)(NEXP + 1) * T_TOK * INTER]; // ~104 MB
__device__ float g_eo  [(size_t)2 * T_TOK * HID];            // ~33.5 MB

// ---------------- helpers ----------------
__device__ __forceinline__ uint32_t f2tf(float f) {
    uint32_t r;
    asm("cvt.rna.tf32.f32 %0, %1;" : "=r"(r) : "f"(f));
    return r;
}

__device__ __forceinline__ void mma_tf32(float* c, const uint32_t* a, const uint32_t* b) {
    asm volatile(
        "mma.sync.aligned.m16n8k8.row.col.f32.tf32.tf32.f32 "
        "{%0,%1,%2,%3}, {%4,%5,%6,%7}, {%8,%9}, {%0,%1,%2,%3};"
        : "+f"(c[0]), "+f"(c[1]), "+f"(c[2]), "+f"(c[3])
        : "r"(a[0]), "r"(a[1]), "r"(a[2]), "r"(a[3]),
          "r"(b[0]), "r"(b[1]));
}

// ---------------- kernel 0: zero counters (graph replays) ----------------
__global__ void zero_cnt_kernel() {
    if (threadIdx.x < NEXP) g_cnt[threadIdx.x] = 0;
}

// ---------------- kernel 1: router ----------------
// One block per token; warp w computes logit for expert w.
__global__ void router_kernel(const float* __restrict__ x,
                              const float* __restrict__ rw) {
    const int t    = blockIdx.x;
    const int lane = threadIdx.x & 31;
    const int wid  = threadIdx.x >> 5;   // expert id 0..7
    const float* xr = x  + (size_t)t   * HID;
    const float* wr = rw + (size_t)wid * HID;
    float s = 0.f;
    for (int i = lane; i < HID; i += 32) s += xr[i] * wr[i];
    #pragma unroll
    for (int o = 16; o; o >>= 1) s += __shfl_xor_sync(0xffffffffu, s, o);
    __shared__ float logits[NEXP];
    if (lane == 0) logits[wid] = s;
    __syncthreads();
    if (threadIdx.x == 0) {
        int i0 = 0; float l0 = logits[0];
        #pragma unroll
        for (int e = 1; e < NEXP; e++) if (logits[e] > l0) { l0 = logits[e]; i0 = e; }
        int i1 = -1; float l1 = -3.4e38f;
        #pragma unroll
        for (int e = 0; e < NEXP; e++) if (e != i0 && logits[e] > l1) { l1 = logits[e]; i1 = e; }
        // renormalized top-2 softmax weights
        float r  = expf(l1 - l0);           // <= 1
        float w0 = 1.f / (1.f + r);
        float w1 = 1.f - w0;
        int p0 = atomicAdd(&g_cnt[i0], 1);
        g_tok[i0 * T_TOK + p0] = t; g_slot[i0 * T_TOK + p0] = 2 * t;     g_wt[i0 * T_TOK + p0] = w0;
        int p1 = atomicAdd(&g_cnt[i1], 1);
        g_tok[i1 * T_TOK + p1] = t; g_slot[i1 * T_TOK + p1] = 2 * t + 1; g_wt[i1 * T_TOK + p1] = w1;
    }
}

// ---------------- kernel 2: grouped dual GEMM (gate & up) + SiLU ----------------
// grid (I/64, T/64, 9): z = expert (8 routed, 8 == shared)
// Block: 128 threads = 4 warps (2x2), warp tile 32x32, BK=32, tf32 mma.
__global__ void __launch_bounds__(128)
gemm1_kernel(const float* __restrict__ x,
             const float* __restrict__ gate_w,
             const float* __restrict__ up_w,
             const float* __restrict__ sgate,
             const float* __restrict__ sup) {
    const int e  = blockIdx.z;
    const int m0 = blockIdx.y * 64;
    const int n0 = blockIdx.x * 64;
    int M, grp;
    const float *gp, *uq;
    if (e < NEXP) {
        M = g_cnt[e];
        if (m0 >= M) return;
        gp  = gate_w + (size_t)e * INTER * HID;
        uq  = up_w   + (size_t)e * INTER * HID;
        grp = e * T_TOK;
    } else {
        M = T_TOK;
        gp = sgate; uq = sup;
        grp = NEXP * T_TOK;
    }

    __shared__ uint32_t As[64][33];
    __shared__ uint32_t Bg[64][33];
    __shared__ uint32_t Bu[64][33];
    __shared__ int tok_s[64];

    const int tid  = threadIdx.x;
    const int lane = tid & 31;
    const int wid  = tid >> 5;
    const int wm   = (wid & 1) * 32;
    const int wn   = (wid >> 1) * 32;
    const int g    = lane >> 2;
    const int tg   = lane & 3;

    if (tid < 64) {
        int r = m0 + tid;
        tok_s[tid] = (e < NEXP) ? ((r < M) ? g_tok[e * T_TOK + r] : 0) : r;
    }
    __syncthreads();

    float cg[2][4][4], cu[2][4][4];
    #pragma unroll
    for (int i = 0; i < 2; i++)
        #pragma unroll
        for (int j = 0; j < 4; j++)
            #pragma unroll
            for (int q = 0; q < 4; q++) { cg[i][j][q] = 0.f; cu[i][j][q] = 0.f; }

    for (int k0 = 0; k0 < HID; k0 += 32) {
        #pragma unroll
        for (int i = 0; i < 4; i++) {
            int f  = tid + i * 128;
            int r  = f >> 3;
            int kc = (f & 7) << 2;
            float4 v;
            v = *(const float4*)(x + (size_t)tok_s[r] * HID + k0 + kc);
            As[r][kc] = f2tf(v.x); As[r][kc+1] = f2tf(v.y);
            As[r][kc+2] = f2tf(v.z); As[r][kc+3] = f2tf(v.w);
            v = *(const float4*)(gp + (size_t)(n0 + r) * HID + k0 + kc);
            Bg[r][kc] = f2tf(v.x); Bg[r][kc+1] = f2tf(v.y);
            Bg[r][kc+2] = f2tf(v.z); Bg[r][kc+3] = f2tf(v.w);
            v = *(const float4*)(uq + (size_t)(n0 + r) * HID + k0 + kc);
            Bu[r][kc] = f2tf(v.x); Bu[r][kc+1] = f2tf(v.y);
            Bu[r][kc+2] = f2tf(v.z); Bu[r][kc+3] = f2tf(v.w);
        }
        __syncthreads();
        #pragma unroll
        for (int ks = 0; ks < 4; ks++) {
            const int kk = ks * 8;
            uint32_t a[2][4];
            #pragma unroll
            for (int mi = 0; mi < 2; mi++) {
                int r = wm + mi * 16;
                a[mi][0] = As[r + g    ][kk + tg];
                a[mi][1] = As[r + g + 8][kk + tg];
                a[mi][2] = As[r + g    ][kk + tg + 4];
                a[mi][3] = As[r + g + 8][kk + tg + 4];
            }
            #pragma unroll
            for (int ni = 0; ni < 4; ni++) {
                int c = wn + ni * 8 + g;
                uint32_t bg[2], bu[2];
                bg[0] = Bg[c][kk + tg]; bg[1] = Bg[c][kk + tg + 4];
                bu[0] = Bu[c][kk + tg]; bu[1] = Bu[c][kk + tg + 4];
                #pragma unroll
                for (int mi = 0; mi < 2; mi++) {
                    mma_tf32(cg[mi][ni], a[mi], bg);
                    mma_tf32(cu[mi][ni], a[mi], bu);
                }
            }
        }
        __syncthreads();
    }

    float* hb = g_hmid + (size_t)grp * INTER;
    #pragma unroll
    for (int mi = 0; mi < 2; mi++) {
        #pragma unroll
        for (int ni = 0; ni < 4; ni++) {
            int col = n0 + wn + ni * 8 + 2 * tg;
            int r0  = m0 + wm + mi * 16 + g;
            int r1  = r0 + 8;
            if (r0 < M) {
                float gv = cg[mi][ni][0], uv = cu[mi][ni][0];
                hb[(size_t)r0 * INTER + col]     = gv / (1.f + __expf(-gv)) * uv;
                gv = cg[mi][ni][1]; uv = cu[mi][ni][1];
                hb[(size_t)r0 * INTER + col + 1] = gv / (1.f + __expf(-gv)) * uv;
            }
            if (r1 < M) {
                float gv = cg[mi][ni][2], uv = cu[mi][ni][2];
                hb[(size_t)r1 * INTER + col]     = gv / (1.f + __expf(-gv)) * uv;
                gv = cg[mi][ni][3]; uv = cu[mi][ni][3];
                hb[(size_t)r1 * INTER + col + 1] = gv / (1.f + __expf(-gv)) * uv;
            }
        }
    }
}

// ---------------- kernel 3: grouped down-projection GEMM ----------------
// is_shared: writes out[t,h] directly (covers all elements).
// routed:    writes w*acc into g_eo[slot, h] (plain stores, deterministic).
__global__ void __launch_bounds__(128)
gemm2_kernel(const float* __restrict__ down_w,
             const float* __restrict__ sdown,
             float* __restrict__ out,
             int is_shared) {
    const int e  = blockIdx.z;
    const int m0 = blockIdx.y * 64;
    const int n0 = blockIdx.x * 64;
    int M, grp;
    const float* bp;
    if (is_shared) {
        M = T_TOK; grp = NEXP * T_TOK; bp = sdown;
    } else {
        M = g_cnt[e];
        if (m0 >= M) return;
        grp = e * T_TOK;
        bp  = down_w + (size_t)e * HID * INTER;
    }

    __shared__ uint32_t As[64][33];
    __shared__ uint32_t Bs[64][33];
    __shared__ int   idx_s[64];
    __shared__ float wt_s[64];

    const int tid  = threadIdx.x;
    const int lane = tid & 31;
    const int wid  = tid >> 5;
    const int wm   = (wid & 1) * 32;
    const int wn   = (wid >> 1) * 32;
    const int g    = lane >> 2;
    const int tg   = lane & 3;

    if (tid < 64) {
        int r = m0 + tid;
        if (is_shared) { idx_s[tid] = r; wt_s[tid] = 1.f; }
        else {
            idx_s[tid] = (r < M) ? g_slot[e * T_TOK + r] : 0;
            wt_s[tid]  = (r < M) ? g_wt  [e * T_TOK + r] : 0.f;
        }
    }
    __syncthreads();

    const float* ab = g_hmid + (size_t)grp * INTER;

    float cc[2][4][4];
    #pragma unroll
    for (int i = 0; i < 2; i++)
        #pragma unroll
        for (int j = 0; j < 4; j++)
            #pragma unroll
            for (int q = 0; q < 4; q++) cc[i][j][q] = 0.f;

    for (int k0 = 0; k0 < INTER; k0 += 32) {
        #pragma unroll
        for (int i = 0; i < 4; i++) {
            int f  = tid + i * 128;
            int r  = f >> 3;
            int kc = (f & 7) << 2;
            int rr = m0 + r; if (rr >= M) rr = m0;   // clamp to valid row
            float4 v;
            v = *(const float4*)(ab + (size_t)rr * INTER + k0 + kc);
            As[r][kc] = f2tf(v.x); As[r][kc+1] = f2tf(v.y);
            As[r][kc+2] = f2tf(v.z); As[r][kc+3] = f2tf(v.w);
            v = *(const float4*)(bp + (size_t)(n0 + r) * INTER + k0 + kc);
            Bs[r][kc] = f2tf(v.x); Bs[r][kc+1] = f2tf(v.y);
            Bs[r][kc+2] = f2tf(v.z); Bs[r][kc+3] = f2tf(v.w);
        }
        __syncthreads();
        #pragma unroll
        for (int ks = 0; ks < 4; ks++) {
            const int kk = ks * 8;
            uint32_t a[2][4];
            #pragma unroll
            for (int mi = 0; mi < 2; mi++) {
                int r = wm + mi * 16;
                a[mi][0] = As[r + g    ][kk + tg];
                a[mi][1] = As[r + g + 8][kk + tg];
                a[mi][2] = As[r + g    ][kk + tg + 4];
                a[mi][3] = As[r + g + 8][kk + tg + 4];
            }
            #pragma unroll
            for (int ni = 0; ni < 4; ni++) {
                int c = wn + ni * 8 + g;
                uint32_t b[2];
                b[0] = Bs[c][kk + tg]; b[1] = Bs[c][kk + tg + 4];
                #pragma unroll
                for (int mi = 0; mi < 2; mi++) mma_tf32(cc[mi][ni], a[mi], b);
            }
        }
        __syncthreads();
    }

    #pragma unroll
    for (int mi = 0; mi < 2; mi++) {
        #pragma unroll
        for (int ni = 0; ni < 4; ni++) {
            int col = n0 + wn + ni * 8 + 2 * tg;
            int rl0 = wm + mi * 16 + g;
            int rl1 = rl0 + 8;
            if (m0 + rl0 < M) {
                int idx = idx_s[rl0]; float w = wt_s[rl0];
                if (is_shared) {
                    float* o = out + (size_t)idx * HID + col;
                    o[0] = cc[mi][ni][0]; o[1] = cc[mi][ni][1];
                } else {
                    float* o = g_eo + (size_t)idx * HID + col;
                    o[0] = w * cc[mi][ni][0]; o[1] = w * cc[mi][ni][1];
                }
            }
            if (m0 + rl1 < M) {
                int idx = idx_s[rl1]; float w = wt_s[rl1];
                if (is_shared) {
                    float* o = out + (size_t)idx * HID + col;
                    o[0] = cc[mi][ni][2]; o[1] = cc[mi][ni][3];
                } else {
                    float* o = g_eo + (size_t)idx * HID + col;
                    o[0] = w * cc[mi][ni][2]; o[1] = w * cc[mi][ni][3];
                }
            }
        }
    }
}

// ---------------- kernel 4: combine routed slots into out ----------------
__global__ void combine_kernel(float* __restrict__ out) {
    int idx = blockIdx.x * blockDim.x + threadIdx.x;       // float4 index
    const int W = HID / 4;
    int t  = idx / W;
    int h4 = idx - t * W;
    float4 o = ((float4*)out)[idx];
    float4 a = ((const float4*)g_eo)[(size_t)(2 * t)     * W + h4];
    float4 b = ((const float4*)g_eo)[(size_t)(2 * t + 1) * W + h4];
    o.x += a.x + b.x; o.y += a.y + b.y; o.z += a.z + b.z; o.w += a.w + b.w;
    ((float4*)out)[idx] = o;
}

// ---------------- launch ----------------
extern "C" void kernel_launch(void* const* d_in, const int* in_sizes, int n_in,
                              void* d_out, int out_size) {
    const float* x        = (const float*)d_in[0];
    const float* router_w = (const float*)d_in[1];
    const float* gate_w   = (const float*)d_in[2];
    const float* up_w     = (const float*)d_in[3];
    const float* down_w   = (const float*)d_in[4];
    const float* sgate    = (const float*)d_in[5];
    const float* sup      = (const float*)d_in[6];
    const float* sdown    = (const float*)d_in[7];
    float* out = (float*)d_out;

    zero_cnt_kernel<<<1, 32>>>();
    router_kernel<<<T_TOK, 256>>>(x, router_w);
    gemm1_kernel<<<dim3(INTER / 64, T_TOK / 64, NEXP + 1), 128>>>(x, gate_w, up_w, sgate, sup);
    gemm2_kernel<<<dim3(HID / 64, T_TOK / 64, 1), 128>>>(down_w, sdown, out, 1);   // shared -> out
    gemm2_kernel<<<dim3(HID / 64, T_TOK / 64, NEXP), 128>>>(down_w, sdown, out, 0); // routed -> eo
    combine_kernel<<<(T_TOK * HID / 4) / 256, 256>>>(out);
}

// round 2
// speedup vs baseline: 1.7563x; 1.7563x over previous
#include <cuda_runtime.h>
#include <cstdint>
#include <math.h>

#define T_TOK 2048
#define HID   2048
#define INTER 1408
#define NEXP  8

// ---------------- device scratch (no allocations allowed) ----------------
__device__ int   g_cnt[NEXP];
__device__ int   g_tok [NEXP * T_TOK];
__device__ int   g_slot[NEXP * T_TOK];
__device__ float g_wt  [NEXP * T_TOK];
__device__ float g_hmid[(size_t)(NEXP + 1) * T_TOK * INTER];
__device__ float g_eo  [(size_t)2 * T_TOK * HID];

// ---------------- helpers ----------------
__device__ __forceinline__ uint32_t f2tf(float f) {
    uint32_t r;
    asm("cvt.rna.tf32.f32 %0, %1;" : "=r"(r) : "f"(f));
    return r;
}

__device__ __forceinline__ void mma_tf32(float* c, const uint32_t* a, const uint32_t* b) {
    asm volatile(
        "mma.sync.aligned.m16n8k8.row.col.f32.tf32.tf32.f32 "
        "{%0,%1,%2,%3}, {%4,%5,%6,%7}, {%8,%9}, {%0,%1,%2,%3};"
        : "+f"(c[0]), "+f"(c[1]), "+f"(c[2]), "+f"(c[3])
        : "r"(a[0]), "r"(a[1]), "r"(a[2]), "r"(a[3]),
          "r"(b[0]), "r"(b[1]));
}

__device__ __forceinline__ uint4 cvt4(float4 v) {
    uint4 r;
    r.x = f2tf(v.x); r.y = f2tf(v.y); r.z = f2tf(v.z); r.w = f2tf(v.w);
    return r;
}

// Fragment-major smem layouts (BM/BN=64, BK=32), conflict-free swizzle.
// A word index: ((mt*4+ks)*4 + s)*32 + 4*((g + 2*ks + q)&7) + c3,  s = half + 2q
// B word index: ((nt*4+ks)*2 + q)*32 + 4*((g + 2*ks + q)&7) + c3
__device__ __forceinline__ int idxA_store(int r, int kc) {
    int mt = r >> 4, half = (r >> 3) & 1, g = r & 7;
    int ks = kc >> 3, q = (kc >> 2) & 1;
    int s = half + 2 * q;
    return (((mt * 4 + ks) * 4 + s) * 32 + 4 * ((g + 2 * ks + q) & 7));
}
__device__ __forceinline__ int idxB_store(int r, int kc) {
    int nt = r >> 3, g = r & 7;
    int ks = kc >> 3, q = (kc >> 2) & 1;
    return (((nt * 4 + ks) * 2 + q) * 32 + 4 * ((g + 2 * ks + q) & 7));
}

// ---------------- kernel 0: zero counters ----------------
__global__ void zero_cnt_kernel() {
    if (threadIdx.x < NEXP) g_cnt[threadIdx.x] = 0;
}

// ---------------- kernel 1: router ----------------
__global__ void router_kernel(const float* __restrict__ x,
                              const float* __restrict__ rw) {
    const int t    = blockIdx.x;
    const int lane = threadIdx.x & 31;
    const int wid  = threadIdx.x >> 5;
    const float* xr = x  + (size_t)t   * HID;
    const float* wr = rw + (size_t)wid * HID;
    float s = 0.f;
    for (int i = lane; i < HID; i += 32) s += xr[i] * wr[i];
    #pragma unroll
    for (int o = 16; o; o >>= 1) s += __shfl_xor_sync(0xffffffffu, s, o);
    __shared__ float logits[NEXP];
    if (lane == 0) logits[wid] = s;
    __syncthreads();
    if (threadIdx.x == 0) {
        int i0 = 0; float l0 = logits[0];
        #pragma unroll
        for (int e = 1; e < NEXP; e++) if (logits[e] > l0) { l0 = logits[e]; i0 = e; }
        int i1 = -1; float l1 = -3.4e38f;
        #pragma unroll
        for (int e = 0; e < NEXP; e++) if (e != i0 && logits[e] > l1) { l1 = logits[e]; i1 = e; }
        float r  = expf(l1 - l0);
        float w0 = 1.f / (1.f + r);
        float w1 = 1.f - w0;
        int p0 = atomicAdd(&g_cnt[i0], 1);
        g_tok[i0 * T_TOK + p0] = t; g_slot[i0 * T_TOK + p0] = 2 * t;     g_wt[i0 * T_TOK + p0] = w0;
        int p1 = atomicAdd(&g_cnt[i1], 1);
        g_tok[i1 * T_TOK + p1] = t; g_slot[i1 * T_TOK + p1] = 2 * t + 1; g_wt[i1 * T_TOK + p1] = w1;
    }
}

// ---------------- kernel 2: grouped dual GEMM (gate & up) + SiLU ----------------
__global__ void __launch_bounds__(128)
gemm1_kernel(const float* __restrict__ x,
             const float* __restrict__ gate_w,
             const float* __restrict__ up_w,
             const float* __restrict__ sgate,
             const float* __restrict__ sup) {
    const int e  = blockIdx.z;
    const int m0 = blockIdx.y * 64;
    const int n0 = blockIdx.x * 64;
    int M, grp;
    const float *gp, *uq;
    if (e < NEXP) {
        M = g_cnt[e];
        if (m0 >= M) return;
        gp  = gate_w + (size_t)e * INTER * HID;
        uq  = up_w   + (size_t)e * INTER * HID;
        grp = e * T_TOK;
    } else {
        M = T_TOK;
        gp = sgate; uq = sup;
        grp = NEXP * T_TOK;
    }

    __shared__ uint32_t As[2048];
    __shared__ uint32_t Bg[2048];
    __shared__ uint32_t Bu[2048];
    __shared__ int tok_s[64];

    const int tid  = threadIdx.x;
    const int lane = tid & 31;
    const int wid  = tid >> 5;
    const int wm   = (wid & 1);          // m-half (0/1) -> mt base = wm*2
    const int wn   = (wid >> 1);         // n-half (0/1) -> nt base = wn*4
    const int g    = lane >> 2;
    const int tg   = lane & 3;

    if (tid < 64) {
        int r = m0 + tid;
        tok_s[tid] = (e < NEXP) ? ((r < M) ? g_tok[e * T_TOK + r] : 0) : r;
    }
    __syncthreads();

    // loader mapping + pointers
    int ia[4], ib[4];
    const float *pA[4], *pG[4], *pU[4];
    #pragma unroll
    for (int i = 0; i < 4; i++) {
        int f  = tid + i * 128;
        int r  = f >> 3;
        int kc = (f & 7) << 2;
        ia[i] = idxA_store(r, kc);
        ib[i] = idxB_store(r, kc);
        pA[i] = x  + (size_t)tok_s[r] * HID + kc;
        pG[i] = gp + (size_t)(n0 + r) * HID + kc;
        pU[i] = uq + (size_t)(n0 + r) * HID + kc;
    }

    float cg[2][4][4], cu[2][4][4];
    #pragma unroll
    for (int i = 0; i < 2; i++)
        #pragma unroll
        for (int j = 0; j < 4; j++)
            #pragma unroll
            for (int q = 0; q < 4; q++) { cg[i][j][q] = 0.f; cu[i][j][q] = 0.f; }

    uint4 va[4], vg[4], vu[4];
    #pragma unroll
    for (int i = 0; i < 4; i++) {
        va[i] = cvt4(*(const float4*)pA[i]);
        vg[i] = cvt4(*(const float4*)pG[i]);
        vu[i] = cvt4(*(const float4*)pU[i]);
    }

    for (int k0 = 0; k0 < HID; k0 += 32) {
        #pragma unroll
        for (int i = 0; i < 4; i++) {
            *(uint4*)&As[ia[i]] = va[i];
            *(uint4*)&Bg[ib[i]] = vg[i];
            *(uint4*)&Bu[ib[i]] = vu[i];
        }
        __syncthreads();
        if (k0 + 32 < HID) {
            #pragma unroll
            for (int i = 0; i < 4; i++) {
                va[i] = cvt4(*(const float4*)(pA[i] + k0 + 32));
                vg[i] = cvt4(*(const float4*)(pG[i] + k0 + 32));
                vu[i] = cvt4(*(const float4*)(pU[i] + k0 + 32));
            }
        }
        #pragma unroll
        for (int ks = 0; ks < 4; ks++) {
            const int off0 = 4 * ((g + 2 * ks) & 7) + tg;
            const int off1 = 4 * ((g + 2 * ks + 1) & 7) + tg;
            uint32_t a[2][4];
            #pragma unroll
            for (int mi = 0; mi < 2; mi++) {
                int mt = wm * 2 + mi;
                int base = ((mt * 4 + ks) * 4) * 32;
                a[mi][0] = As[base + off0];
                a[mi][1] = As[base + 32 + off0];
                a[mi][2] = As[base + 64 + off1];
                a[mi][3] = As[base + 96 + off1];
            }
            #pragma unroll
            for (int ni = 0; ni < 4; ni++) {
                int nt = wn * 4 + ni;
                int baseB = ((nt * 4 + ks) * 2) * 32;
                uint32_t bg[2], bu[2];
                bg[0] = Bg[baseB + off0]; bg[1] = Bg[baseB + 32 + off1];
                bu[0] = Bu[baseB + off0]; bu[1] = Bu[baseB + 32 + off1];
                #pragma unroll
                for (int mi = 0; mi < 2; mi++) {
                    mma_tf32(cg[mi][ni], a[mi], bg);
                    mma_tf32(cu[mi][ni], a[mi], bu);
                }
            }
        }
        __syncthreads();
    }

    float* hb = g_hmid + (size_t)grp * INTER;
    #pragma unroll
    for (int mi = 0; mi < 2; mi++) {
        #pragma unroll
        for (int ni = 0; ni < 4; ni++) {
            int col = n0 + (wn * 4 + ni) * 8 + 2 * tg;
            int r0  = m0 + (wm * 2 + mi) * 16 + g;
            int r1  = r0 + 8;
            if (r0 < M) {
                float gv = cg[mi][ni][0], uv = cu[mi][ni][0];
                hb[(size_t)r0 * INTER + col]     = gv / (1.f + __expf(-gv)) * uv;
                gv = cg[mi][ni][1]; uv = cu[mi][ni][1];
                hb[(size_t)r0 * INTER + col + 1] = gv / (1.f + __expf(-gv)) * uv;
            }
            if (r1 < M) {
                float gv = cg[mi][ni][2], uv = cu[mi][ni][2];
                hb[(size_t)r1 * INTER + col]     = gv / (1.f + __expf(-gv)) * uv;
                gv = cg[mi][ni][3]; uv = cu[mi][ni][3];
                hb[(size_t)r1 * INTER + col + 1] = gv / (1.f + __expf(-gv)) * uv;
            }
        }
    }
}

// ---------------- kernel 3: grouped down-projection GEMM (merged) ----------------
// z = 0..7 routed (writes w*acc to g_eo slots), z = 8 shared (writes out directly)
__global__ void __launch_bounds__(128)
gemm2_kernel(const float* __restrict__ down_w,
             const float* __restrict__ sdown,
             float* __restrict__ out) {
    const int e  = blockIdx.z;
    const int m0 = blockIdx.y * 64;
    const int n0 = blockIdx.x * 64;
    const int is_shared = (e == NEXP);
    int M, grp;
    const float* bp;
    if (is_shared) {
        M = T_TOK; grp = NEXP * T_TOK; bp = sdown;
    } else {
        M = g_cnt[e];
        if (m0 >= M) return;
        grp = e * T_TOK;
        bp  = down_w + (size_t)e * HID * INTER;
    }

    __shared__ uint32_t As[2048];
    __shared__ uint32_t Bs[2048];
    __shared__ int   idx_s[64];
    __shared__ float wt_s[64];

    const int tid  = threadIdx.x;
    const int lane = tid & 31;
    const int wid  = tid >> 5;
    const int wm   = (wid & 1);
    const int wn   = (wid >> 1);
    const int g    = lane >> 2;
    const int tg   = lane & 3;

    if (tid < 64) {
        int r = m0 + tid;
        if (is_shared) { idx_s[tid] = r; wt_s[tid] = 1.f; }
        else {
            idx_s[tid] = (r < M) ? g_slot[e * T_TOK + r] : 0;
            wt_s[tid]  = (r < M) ? g_wt  [e * T_TOK + r] : 0.f;
        }
    }
    __syncthreads();

    const float* ab = g_hmid + (size_t)grp * INTER;

    int ia[4], ib[4];
    const float *pA[4], *pB[4];
    #pragma unroll
    for (int i = 0; i < 4; i++) {
        int f  = tid + i * 128;
        int r  = f >> 3;
        int kc = (f & 7) << 2;
        ia[i] = idxA_store(r, kc);
        ib[i] = idxB_store(r, kc);
        int rr = m0 + r; if (rr >= M) rr = m0;
        pA[i] = ab + (size_t)rr * INTER + kc;
        pB[i] = bp + (size_t)(n0 + r) * INTER + kc;
    }

    float cc[2][4][4];
    #pragma unroll
    for (int i = 0; i < 2; i++)
        #pragma unroll
        for (int j = 0; j < 4; j++)
            #pragma unroll
            for (int q = 0; q < 4; q++) cc[i][j][q] = 0.f;

    uint4 va[4], vb[4];
    #pragma unroll
    for (int i = 0; i < 4; i++) {
        va[i] = cvt4(*(const float4*)pA[i]);
        vb[i] = cvt4(*(const float4*)pB[i]);
    }

    for (int k0 = 0; k0 < INTER; k0 += 32) {
        #pragma unroll
        for (int i = 0; i < 4; i++) {
            *(uint4*)&As[ia[i]] = va[i];
            *(uint4*)&Bs[ib[i]] = vb[i];
        }
        __syncthreads();
        if (k0 + 32 < INTER) {
            #pragma unroll
            for (int i = 0; i < 4; i++) {
                va[i] = cvt4(*(const float4*)(pA[i] + k0 + 32));
                vb[i] = cvt4(*(const float4*)(pB[i] + k0 + 32));
            }
        }
        #pragma unroll
        for (int ks = 0; ks < 4; ks++) {
            const int off0 = 4 * ((g + 2 * ks) & 7) + tg;
            const int off1 = 4 * ((g + 2 * ks + 1) & 7) + tg;
            uint32_t a[2][4];
            #pragma unroll
            for (int mi = 0; mi < 2; mi++) {
                int mt = wm * 2 + mi;
                int base = ((mt * 4 + ks) * 4) * 32;
                a[mi][0] = As[base + off0];
                a[mi][1] = As[base + 32 + off0];
                a[mi][2] = As[base + 64 + off1];
                a[mi][3] = As[base + 96 + off1];
            }
            #pragma unroll
            for (int ni = 0; ni < 4; ni++) {
                int nt = wn * 4 + ni;
                int baseB = ((nt * 4 + ks) * 2) * 32;
                uint32_t b[2];
                b[0] = Bs[baseB + off0]; b[1] = Bs[baseB + 32 + off1];
                #pragma unroll
                for (int mi = 0; mi < 2; mi++) mma_tf32(cc[mi][ni], a[mi], b);
            }
        }
        __syncthreads();
    }

    #pragma unroll
    for (int mi = 0; mi < 2; mi++) {
        #pragma unroll
        for (int ni = 0; ni < 4; ni++) {
            int col = n0 + (wn * 4 + ni) * 8 + 2 * tg;
            int rl0 = (wm * 2 + mi) * 16 + g;
            int rl1 = rl0 + 8;
            if (m0 + rl0 < M) {
                int idx = idx_s[rl0]; float w = wt_s[rl0];
                if (is_shared) {
                    float* o = out + (size_t)idx * HID + col;
                    o[0] = cc[mi][ni][0]; o[1] = cc[mi][ni][1];
                } else {
                    float* o = g_eo + (size_t)idx * HID + col;
                    o[0] = w * cc[mi][ni][0]; o[1] = w * cc[mi][ni][1];
                }
            }
            if (m0 + rl1 < M) {
                int idx = idx_s[rl1]; float w = wt_s[rl1];
                if (is_shared) {
                    float* o = out + (size_t)idx * HID + col;
                    o[0] = cc[mi][ni][2]; o[1] = cc[mi][ni][3];
                } else {
                    float* o = g_eo + (size_t)idx * HID + col;
                    o[0] = w * cc[mi][ni][2]; o[1] = w * cc[mi][ni][3];
                }
            }
        }
    }
}

// ---------------- kernel 4: combine routed slots into out ----------------
__global__ void combine_kernel(float* __restrict__ out) {
    int idx = blockIdx.x * blockDim.x + threadIdx.x;
    const int W = HID / 4;
    int t  = idx / W;
    int h4 = idx - t * W;
    float4 o = ((float4*)out)[idx];
    float4 a = ((const float4*)g_eo)[(size_t)(2 * t)     * W + h4];
    float4 b = ((const float4*)g_eo)[(size_t)(2 * t + 1) * W + h4];
    o.x += a.x + b.x; o.y += a.y + b.y; o.z += a.z + b.z; o.w += a.w + b.w;
    ((float4*)out)[idx] = o;
}

// ---------------- launch ----------------
extern "C" void kernel_launch(void* const* d_in, const int* in_sizes, int n_in,
                              void* d_out, int out_size) {
    const float* x        = (const float*)d_in[0];
    const float* router_w = (const float*)d_in[1];
    const float* gate_w   = (const float*)d_in[2];
    const float* up_w     = (const float*)d_in[3];
    const float* down_w   = (const float*)d_in[4];
    const float* sgate    = (const float*)d_in[5];
    const float* sup      = (const float*)d_in[6];
    const float* sdown    = (const float*)d_in[7];
    float* out = (float*)d_out;

    zero_cnt_kernel<<<1, 32>>>();
    router_kernel<<<T_TOK, 256>>>(x, router_w);
    gemm1_kernel<<<dim3(INTER / 64, T_TOK / 64, NEXP + 1), 128>>>(x, gate_w, up_w, sgate, sup);
    gemm2_kernel<<<dim3(HID / 64, T_TOK / 64, NEXP + 1), 128>>>(down_w, sdown, out);
    combine_kernel<<<(T_TOK * HID / 4) / 256, 256>>>(out);
}

// round 4
// speedup vs baseline: 4.3081x; 2.4529x over previous
#include <cuda_runtime.h>
#include <cuda_fp16.h>
#include <cstdint>
#include <math.h>

#define T_TOK 2048
#define HID   2048
#define INTER 1408
#define NEXP  8

// fp16 weight blob layout (element offsets)
#define GATE_SZ ((size_t)NEXP * INTER * HID)
#define SH_SZ   ((size_t)INTER * HID)
#define UP_OFF   (GATE_SZ)
#define DOWN_OFF (2 * GATE_SZ)
#define SG_OFF   (3 * GATE_SZ)
#define SU_OFF   (SG_OFF + SH_SZ)
#define SD_OFF   (SU_OFF + SH_SZ)
#define W16_TOTAL (SD_OFF + SH_SZ)

// ---------------- device scratch ----------------
__device__ __half g_w16[W16_TOTAL];                       // ~156 MB
__device__ __half g_x16[(size_t)T_TOK * HID];
__device__ __half g_hmid[(size_t)(NEXP + 1) * T_TOK * INTER];
__device__ int    g_cnt[NEXP];
__device__ int    g_tok [NEXP * T_TOK];
__device__ int    g_slot[NEXP * T_TOK];
__device__ float  g_wt  [NEXP * T_TOK];
__device__ float  g_eo  [(size_t)2 * T_TOK * HID];

// ---------------- helpers ----------------
__device__ __forceinline__ uint32_t smem_u32(const void* p) {
    uint32_t a;
    asm("{ .reg .u64 t; cvta.to.shared.u64 t, %1; cvt.u32.u64 %0, t; }" : "=r"(a) : "l"(p));
    return a;
}
// 64B-row tile swizzle: 16B slot column XOR'ed with row bits (conflict-free
// for both cp.async 16B stores and ldmatrix row gathers; verified by bank enum)
__device__ __forceinline__ uint32_t swz(int r, int cb) {
    return (uint32_t)((r << 6) + ((((cb >> 4) ^ ((r >> 1) & 3)) << 4) | (cb & 15)));
}
__device__ __forceinline__ void cpa(uint32_t dst, const void* src) {
    asm volatile("cp.async.cg.shared.global [%0], [%1], 16;" :: "r"(dst), "l"(src));
}
#define CP_COMMIT()  asm volatile("cp.async.commit_group;")
#define CP_WAIT1()   asm volatile("cp.async.wait_group 1;")
#define CP_WAIT0()   asm volatile("cp.async.wait_group 0;")

__device__ __forceinline__ void ldsm4(uint32_t* r, uint32_t a) {
    asm volatile("ldmatrix.sync.aligned.m8n8.x4.shared.b16 {%0,%1,%2,%3}, [%4];"
        : "=r"(r[0]), "=r"(r[1]), "=r"(r[2]), "=r"(r[3]) : "r"(a));
}
__device__ __forceinline__ void mma16816(float* c, const uint32_t* a, const uint32_t* b) {
    asm volatile(
        "mma.sync.aligned.m16n8k16.row.col.f32.f16.f16.f32 "
        "{%0,%1,%2,%3}, {%4,%5,%6,%7}, {%8,%9}, {%0,%1,%2,%3};"
        : "+f"(c[0]), "+f"(c[1]), "+f"(c[2]), "+f"(c[3])
        : "r"(a[0]), "r"(a[1]), "r"(a[2]), "r"(a[3]), "r"(b[0]), "r"(b[1]));
}

// ---------------- zero counters ----------------
__global__ void zero_cnt_kernel() {
    if (threadIdx.x < NEXP) g_cnt[threadIdx.x] = 0;
}

// ---------------- fp32 -> fp16 converters ----------------
__device__ __forceinline__ uint32_t h2u(__half2 h) {
    return *reinterpret_cast<uint32_t*>(&h);
}
__global__ void convw_kernel(const float* __restrict__ src, size_t off, int n8) {
    int i = blockIdx.x * 256 + threadIdx.x;
    if (i >= n8) return;
    const float4* s = (const float4*)src;
    float4 v0 = s[2 * i], v1 = s[2 * i + 1];
    uint4 o;
    o.x = h2u(__floats2half2_rn(v0.x, v0.y));
    o.y = h2u(__floats2half2_rn(v0.z, v0.w));
    o.z = h2u(__floats2half2_rn(v1.x, v1.y));
    o.w = h2u(__floats2half2_rn(v1.z, v1.w));
    ((uint4*)(g_w16 + off))[i] = o;
}
__global__ void convx_kernel(const float* __restrict__ src, int n8) {
    int i = blockIdx.x * 256 + threadIdx.x;
    if (i >= n8) return;
    const float4* s = (const float4*)src;
    float4 v0 = s[2 * i], v1 = s[2 * i + 1];
    uint4 o;
    o.x = h2u(__floats2half2_rn(v0.x, v0.y));
    o.y = h2u(__floats2half2_rn(v0.z, v0.w));
    o.z = h2u(__floats2half2_rn(v1.x, v1.y));
    o.w = h2u(__floats2half2_rn(v1.z, v1.w));
    ((uint4*)g_x16)[i] = o;
}

// ---------------- router ----------------
__global__ void router_kernel(const float* __restrict__ x,
                              const float* __restrict__ rw) {
    const int t    = blockIdx.x;
    const int lane = threadIdx.x & 31;
    const int wid  = threadIdx.x >> 5;
    const float* xr = x  + (size_t)t   * HID;
    const float* wr = rw + (size_t)wid * HID;
    float s = 0.f;
    for (int i = lane; i < HID; i += 32) s += xr[i] * wr[i];
    #pragma unroll
    for (int o = 16; o; o >>= 1) s += __shfl_xor_sync(0xffffffffu, s, o);
    __shared__ float logits[NEXP];
    if (lane == 0) logits[wid] = s;
    __syncthreads();
    if (threadIdx.x == 0) {
        int i0 = 0; float l0 = logits[0];
        #pragma unroll
        for (int e = 1; e < NEXP; e++) if (logits[e] > l0) { l0 = logits[e]; i0 = e; }
        int i1 = -1; float l1 = -3.4e38f;
        #pragma unroll
        for (int e = 0; e < NEXP; e++) if (e != i0 && logits[e] > l1) { l1 = logits[e]; i1 = e; }
        float r  = expf(l1 - l0);
        float w0 = 1.f / (1.f + r);
        float w1 = 1.f - w0;
        int p0 = atomicAdd(&g_cnt[i0], 1);
        g_tok[i0 * T_TOK + p0] = t; g_slot[i0 * T_TOK + p0] = 2 * t;     g_wt[i0 * T_TOK + p0] = w0;
        int p1 = atomicAdd(&g_cnt[i1], 1);
        g_tok[i1 * T_TOK + p1] = t; g_slot[i1 * T_TOK + p1] = 2 * t + 1; g_wt[i1 * T_TOK + p1] = w1;
    }
}

// ---------------- gemm1: M128 x N64(of INTER), warps 0-3 gate / 4-7 up ----------------
#define KB1 (HID / 32)
__global__ void __launch_bounds__(256)
gemm1_f16() {
    const int e  = blockIdx.z;
    const int m0 = blockIdx.y * 128;
    const int n0 = blockIdx.x * 64;
    int M; size_t grp;
    const __half *bgp, *bup;
    if (e < NEXP) {
        M = g_cnt[e];
        if (m0 >= M) return;
        bgp = g_w16 + (size_t)e * INTER * HID;
        bup = g_w16 + UP_OFF + (size_t)e * INTER * HID;
        grp = (size_t)e * T_TOK;
    } else {
        M = T_TOK;
        bgp = g_w16 + SG_OFF; bup = g_w16 + SU_OFF;
        grp = (size_t)NEXP * T_TOK;
    }

    __shared__ __align__(16) char sm[2][16384];   // per stage: A 8KB | Bg 4KB | Bu 4KB
    __shared__ int tok_s[128];

    const int tid = threadIdx.x, lane = tid & 31, wid = tid >> 5;
    if (tid < 128) {
        int r = m0 + tid;
        tok_s[tid] = (e < NEXP) ? ((r < M) ? g_tok[e * T_TOK + r] : 0) : r;
    }
    __syncthreads();

    const uint32_t sb = smem_u32(sm);

    // loaders: 4 x 16B cp.async per thread per stage
    const int lrow = tid >> 2;
    const int cseg = tid & 3;
    const __half* aS0 = g_x16 + (size_t)tok_s[lrow]      * HID + cseg * 8;
    const __half* aS1 = g_x16 + (size_t)tok_s[64 + lrow] * HID + cseg * 8;
    const __half* gS  = bgp + (size_t)(n0 + lrow) * HID + cseg * 8;
    const __half* uS  = bup + (size_t)(n0 + lrow) * HID + cseg * 8;
    const uint32_t aD0 = swz(lrow,      cseg * 16);
    const uint32_t aD1 = swz(64 + lrow, cseg * 16);
    const uint32_t bD  = swz(lrow,      cseg * 16);

    // warp tiling: 64(M) x 32(N) per warp; wid<4 gate, wid>=4 up (same coords)
    const int widl = wid & 3;
    const int wm = (widl & 1) * 64;
    const int wn = (widl >> 1) * 32;
    const uint32_t breg = (wid < 4) ? 8192u : 12288u;
    const int lr   = lane & 7;
    const int arow = ((lane >> 3) & 1) * 8 + lr;
    const int acbx = (lane >> 4) * 16;
    const int brow = (lane >> 4) * 8 + lr;
    const int bcbx = ((lane >> 3) & 1) * 16;

    float c[4][4][4];
    #pragma unroll
    for (int i = 0; i < 4; i++)
        #pragma unroll
        for (int j = 0; j < 4; j++)
            #pragma unroll
            for (int q = 0; q < 4; q++) c[i][j][q] = 0.f;

    #define G1_LOAD(i, buf) { \
        uint32_t s_ = sb + (uint32_t)(buf) * 16384u; int k0_ = (i) * 32; \
        cpa(s_ + aD0, aS0 + k0_); cpa(s_ + aD1, aS1 + k0_); \
        cpa(s_ + 8192u + bD, gS + k0_); cpa(s_ + 12288u + bD, uS + k0_); \
        CP_COMMIT(); }

    G1_LOAD(0, 0);
    for (int i = 0; i < KB1; i++) {
        if (i + 1 < KB1) { G1_LOAD(i + 1, (i + 1) & 1); CP_WAIT1(); }
        else             { CP_WAIT0(); }
        __syncthreads();
        const uint32_t sA = sb + (uint32_t)(i & 1) * 16384u;
        const uint32_t sB = sA + breg;
        #pragma unroll
        for (int ks = 0; ks < 2; ks++) {
            const int kb = ks * 32;
            uint32_t a[4][4], b[4][2];
            #pragma unroll
            for (int mt = 0; mt < 4; mt++)
                ldsm4(a[mt], sA + swz(wm + mt * 16 + arow, kb + acbx));
            #pragma unroll
            for (int p = 0; p < 2; p++) {
                uint32_t t4[4];
                ldsm4(t4, sB + swz(wn + p * 16 + brow, kb + bcbx));
                b[2*p][0] = t4[0]; b[2*p][1] = t4[1];
                b[2*p+1][0] = t4[2]; b[2*p+1][1] = t4[3];
            }
            #pragma unroll
            for (int mt = 0; mt < 4; mt++)
                #pragma unroll
                for (int nt = 0; nt < 4; nt++)
                    mma16816(c[mt][nt], a[mt], b[nt]);
        }
        __syncthreads();
    }

    // epilogue: up warps stash u in smem (half2), gate warps do silu(g)*u -> hmid fp16
    __half2* us = (__half2*)sm;   // [128][32] half2 = 16KB
    if (wid >= 4) {
        #pragma unroll
        for (int mt = 0; mt < 4; mt++)
            #pragma unroll
            for (int nt = 0; nt < 4; nt++) {
                int row = wm + mt * 16 + (lane >> 2);
                int c2  = (wn + nt * 8 + 2 * (lane & 3)) >> 1;
                us[row * 32 + c2]       = __floats2half2_rn(c[mt][nt][0], c[mt][nt][1]);
                us[(row + 8) * 32 + c2] = __floats2half2_rn(c[mt][nt][2], c[mt][nt][3]);
            }
    }
    __syncthreads();
    if (wid < 4) {
        __half* hb = g_hmid + grp * INTER;
        #pragma unroll
        for (int mt = 0; mt < 4; mt++)
            #pragma unroll
            for (int nt = 0; nt < 4; nt++) {
                int row  = wm + mt * 16 + (lane >> 2);
                int lcol = wn + nt * 8 + 2 * (lane & 3);
                int gcol = n0 + lcol;
                #pragma unroll
                for (int h = 0; h < 2; h++) {
                    int rr = row + 8 * h;
                    if (m0 + rr < M) {
                        float2 uv = __half22float2(us[rr * 32 + (lcol >> 1)]);
                        float g0 = c[mt][nt][2 * h], g1 = c[mt][nt][2 * h + 1];
                        float h0 = g0 / (1.f + __expf(-g0)) * uv.x;
                        float h1 = g1 / (1.f + __expf(-g1)) * uv.y;
                        *(__half2*)(hb + (size_t)(m0 + rr) * INTER + gcol) = __floats2half2_rn(h0, h1);
                    }
                }
            }
    }
}

// ---------------- gemm2: M128 x N128(of HID), 8 warps 2x4 ----------------
#define KB2 (INTER / 32)
__global__ void __launch_bounds__(256)
gemm2_f16(float* __restrict__ out) {
    const int e  = blockIdx.z;
    const int m0 = blockIdx.y * 128;
    const int n0 = blockIdx.x * 128;
    const int is_shared = (e == NEXP);
    int M; size_t grp;
    const __half* bp;
    if (is_shared) {
        M = T_TOK; grp = (size_t)NEXP * T_TOK; bp = g_w16 + SD_OFF;
    } else {
        M = g_cnt[e];
        if (m0 >= M) return;
        grp = (size_t)e * T_TOK;
        bp  = g_w16 + DOWN_OFF + (size_t)e * HID * INTER;
    }

    __shared__ __align__(16) char sm[2][16384];  // per stage: A 8KB | B 8KB
    __shared__ int   idx_s[128];
    __shared__ float wt_s[128];

    const int tid = threadIdx.x, lane = tid & 31, wid = tid >> 5;
    if (tid < 128) {
        int r = m0 + tid;
        if (is_shared) { idx_s[tid] = r; wt_s[tid] = 1.f; }
        else {
            idx_s[tid] = (r < M) ? g_slot[e * T_TOK + r] : 0;
            wt_s[tid]  = (r < M) ? g_wt  [e * T_TOK + r] : 0.f;
        }
    }
    __syncthreads();

    const uint32_t sb = smem_u32(sm);
    const __half* hb = g_hmid + grp * INTER;

    const int lrow = tid >> 2;
    const int cseg = tid & 3;
    int rA0 = m0 + lrow;      if (rA0 >= M) rA0 = m0;
    int rA1 = m0 + 64 + lrow; if (rA1 >= M) rA1 = m0;
    const __half* aS0 = hb + (size_t)rA0 * INTER + cseg * 8;
    const __half* aS1 = hb + (size_t)rA1 * INTER + cseg * 8;
    const __half* bS0 = bp + (size_t)(n0 + lrow)      * INTER + cseg * 8;
    const __half* bS1 = bp + (size_t)(n0 + 64 + lrow) * INTER + cseg * 8;
    const uint32_t aD0 = swz(lrow,      cseg * 16);
    const uint32_t aD1 = swz(64 + lrow, cseg * 16);

    const int wm = (wid & 1) * 64;
    const int wn = (wid >> 1) * 32;
    const int lr   = lane & 7;
    const int arow = ((lane >> 3) & 1) * 8 + lr;
    const int acbx = (lane >> 4) * 16;
    const int brow = (lane >> 4) * 8 + lr;
    const int bcbx = ((lane >> 3) & 1) * 16;

    float c[4][4][4];
    #pragma unroll
    for (int i = 0; i < 4; i++)
        #pragma unroll
        for (int j = 0; j < 4; j++)
            #pragma unroll
            for (int q = 0; q < 4; q++) c[i][j][q] = 0.f;

    #define G2_LOAD(i, buf) { \
        uint32_t s_ = sb + (uint32_t)(buf) * 16384u; int k0_ = (i) * 32; \
        cpa(s_ + aD0, aS0 + k0_); cpa(s_ + aD1, aS1 + k0_); \
        cpa(s_ + 8192u + aD0, bS0 + k0_); cpa(s_ + 8192u + aD1, bS1 + k0_); \
        CP_COMMIT(); }

    G2_LOAD(0, 0);
    for (int i = 0; i < KB2; i++) {
        if (i + 1 < KB2) { G2_LOAD(i + 1, (i + 1) & 1); CP_WAIT1(); }
        else             { CP_WAIT0(); }
        __syncthreads();
        const uint32_t sA = sb + (uint32_t)(i & 1) * 16384u;
        const uint32_t sB = sA + 8192u;
        #pragma unroll
        for (int ks = 0; ks < 2; ks++) {
            const int kb = ks * 32;
            uint32_t a[4][4], b[4][2];
            #pragma unroll
            for (int mt = 0; mt < 4; mt++)
                ldsm4(a[mt], sA + swz(wm + mt * 16 + arow, kb + acbx));
            #pragma unroll
            for (int p = 0; p < 2; p++) {
                uint32_t t4[4];
                ldsm4(t4, sB + swz(wn + p * 16 + brow, kb + bcbx));
                b[2*p][0] = t4[0]; b[2*p][1] = t4[1];
                b[2*p+1][0] = t4[2]; b[2*p+1][1] = t4[3];
            }
            #pragma unroll
            for (int mt = 0; mt < 4; mt++)
                #pragma unroll
                for (int nt = 0; nt < 4; nt++)
                    mma16816(c[mt][nt], a[mt], b[nt]);
        }
        __syncthreads();
    }

    float* obase = is_shared ? out : g_eo;
    #pragma unroll
    for (int mt = 0; mt < 4; mt++)
        #pragma unroll
        for (int nt = 0; nt < 4; nt++) {
            int row  = wm + mt * 16 + (lane >> 2);
            int gcol = n0 + wn + nt * 8 + 2 * (lane & 3);
            #pragma unroll
            for (int h = 0; h < 2; h++) {
                int rr = row + 8 * h;
                if (m0 + rr < M) {
                    float w  = wt_s[rr];
                    int   sl = idx_s[rr];
                    float2 o;
                    o.x = w * c[mt][nt][2 * h];
                    o.y = w * c[mt][nt][2 * h + 1];
                    *(float2*)(obase + (size_t)sl * HID + gcol) = o;
                }
            }
        }
}

// ---------------- combine ----------------
__global__ void combine_kernel(float* __restrict__ out) {
    int idx = blockIdx.x * blockDim.x + threadIdx.x;
    const int W = HID / 4;
    int t  = idx / W;
    int h4 = idx - t * W;
    float4 o = ((float4*)out)[idx];
    float4 a = ((const float4*)g_eo)[(size_t)(2 * t)     * W + h4];
    float4 b = ((const float4*)g_eo)[(size_t)(2 * t + 1) * W + h4];
    o.x += a.x + b.x; o.y += a.y + b.y; o.z += a.z + b.z; o.w += a.w + b.w;
    ((float4*)out)[idx] = o;
}

// ---------------- launch ----------------
extern "C" void kernel_launch(void* const* d_in, const int* in_sizes, int n_in,
                              void* d_out, int out_size) {
    const float* x        = (const float*)d_in[0];
    const float* router_w = (const float*)d_in[1];
    const float* gate_w   = (const float*)d_in[2];
    const float* up_w     = (const float*)d_in[3];
    const float* down_w   = (const float*)d_in[4];
    const float* sgate    = (const float*)d_in[5];
    const float* sup      = (const float*)d_in[6];
    const float* sdown    = (const float*)d_in[7];
    float* out = (float*)d_out;

    zero_cnt_kernel<<<1, 32>>>();
    convx_kernel<<<(T_TOK * HID / 8) / 256, 256>>>(x, T_TOK * HID / 8);
    convw_kernel<<<(int)(GATE_SZ / 8 / 256), 256>>>(gate_w, 0,        (int)(GATE_SZ / 8));
    convw_kernel<<<(int)(GATE_SZ / 8 / 256), 256>>>(up_w,   UP_OFF,   (int)(GATE_SZ / 8));
    convw_kernel<<<(int)(GATE_SZ / 8 / 256), 256>>>(down_w, DOWN_OFF, (int)(GATE_SZ / 8));
    convw_kernel<<<(int)(SH_SZ / 8 / 256), 256>>>(sgate, SG_OFF, (int)(SH_SZ / 8));
    convw_kernel<<<(int)(SH_SZ / 8 / 256), 256>>>(sup,   SU_OFF, (int)(SH_SZ / 8));
    convw_kernel<<<(int)(SH_SZ / 8 / 256), 256>>>(sdown, SD_OFF, (int)(SH_SZ / 8));
    router_kernel<<<T_TOK, 256>>>(x, router_w);
    gemm1_f16<<<dim3(INTER / 64, T_TOK / 128, NEXP + 1), 256>>>();
    gemm2_f16<<<dim3(HID / 128, T_TOK / 128, NEXP + 1), 256>>>(out);
    combine_kernel<<<(T_TOK * HID / 4) / 256, 256>>>(out);
}